// round 6
// baseline (speedup 1.0000x reference)
#include <cuda_runtime.h>
#include <cuda_bf16.h>

#define LDIM 4096
#define BDIM 32
#define CIN  64
#define ODIM 128
#define KDIM 9
#define CCHUNKS 4               // split-K chunks over channel dim
#define CPER   (CIN / CCHUNKS)  // 16 channels per chunk
#define OCHUNK 64               // outputs per main-kernel block
#define WSTRIDE 12              // padded weight row: w0..w8, bias, pad, pad

// Scratch (allocation-free rule: __device__ globals)
__device__ float g_part[CCHUNKS * BDIM * LDIM];   // partial channel sums, 2 MB
__device__ float g_adj[BDIM * KDIM * LDIM];       // gathered+scaled adj, 4.7 MB
__device__ float g_wcn[ODIM * KDIM];              // normalized weight_coeff
__device__ float g_evinv;                         // 1 / ||err_vector||

// ---------------------------------------------------------------------------
// Kernel A: split-K channel reduction (512 blocks x 256 thr) + prep (block 512)
//   blocks 0..511: g_part[cc][b][lt*1024 .. +1024) = sum over 16 channels
// ---------------------------------------------------------------------------
__global__ __launch_bounds__(256) void reduce_prep_kernel(
    const float* __restrict__ x,
    const float* __restrict__ wc,
    const float* __restrict__ ev) {

    const int bx = blockIdx.x;
    const int t  = threadIdx.x;

    if (bx < BDIM * 16) {                      // 512 reduce blocks
        const int b   = bx >> 4;               // 0..31
        const int sub = bx & 15;
        const int lt  = sub >> 2;              // l-tile 0..3 (256 float4 each)
        const int cc  = sub & 3;               // channel chunk 0..3
        const int l4  = lt * 256 + t;          // 0..1023

        const float4* xp = reinterpret_cast<const float4*>(x) +
                           ((size_t)b * CIN + cc * CPER) * (LDIM / 4) + l4;
        float4 a0 = make_float4(0.f, 0.f, 0.f, 0.f);
        float4 a1 = make_float4(0.f, 0.f, 0.f, 0.f);
#pragma unroll
        for (int i = 0; i < CPER; i += 2) {    // 8 iters, 2 independent chains
            float4 v0 = __ldg(xp + (i    ) * (LDIM / 4));
            float4 v1 = __ldg(xp + (i + 1) * (LDIM / 4));
            a0.x += v0.x; a0.y += v0.y; a0.z += v0.z; a0.w += v0.w;
            a1.x += v1.x; a1.y += v1.y; a1.z += v1.z; a1.w += v1.w;
        }
        a0.x += a1.x; a0.y += a1.y; a0.z += a1.z; a0.w += a1.w;
        reinterpret_cast<float4*>(g_part)[(cc * BDIM + b) * (LDIM / 4) + l4] = a0;
        return;
    }

    // ---- prep block (256 threads) ----
    __shared__ float red[256];
    float ssq = 0.f;
    for (int i = t; i < LDIM; i += 256) { float v = ev[i]; ssq += v * v; }
    red[t] = ssq;
    __syncthreads();
    for (int s = 128; s > 0; s >>= 1) {
        if (t < s) red[t] += red[t + s];
        __syncthreads();
    }
    if (t == 0) g_evinv = rsqrtf(red[0]);

    if (t < ODIM) {
        float w[KDIM];
        float n = 0.f;
#pragma unroll
        for (int k = 0; k < KDIM; ++k) { w[k] = wc[t * KDIM + k]; n += w[k] * w[k]; }
        float inv = rsqrtf(n);
#pragma unroll
        for (int k = 0; k < KDIM; ++k) g_wcn[t * KDIM + k] = w[k] * inv;
    }
}

// ---------------------------------------------------------------------------
// Kernel B: adj[b,k,l] = xs[b, idx[k,l]] * ev[l]/||ev||, gathers happen ONCE
// grid: (8 l-tiles of 512, 32 b) = 256 blocks x 256 thr, lpt=2
// ---------------------------------------------------------------------------
__global__ __launch_bounds__(256) void gather_kernel(
    const int*   __restrict__ idxm,
    const float* __restrict__ ev) {

    __shared__ float s_xs[LDIM];               // 16 KB

    const int tile = blockIdx.x;               // 0..7
    const int b    = blockIdx.y;               // 0..31
    const int t    = threadIdx.x;

    {   // stage xs[b] = sum of 4 split-K partials (L2-resident)
        float4* s4 = reinterpret_cast<float4*>(s_xs);
        const float4* g4 = reinterpret_cast<const float4*>(g_part);
#pragma unroll
        for (int i = t; i < LDIM / 4; i += 256) {
            float4 p0 = __ldg(&g4[(0 * BDIM + b) * (LDIM / 4) + i]);
            float4 p1 = __ldg(&g4[(1 * BDIM + b) * (LDIM / 4) + i]);
            float4 p2 = __ldg(&g4[(2 * BDIM + b) * (LDIM / 4) + i]);
            float4 p3 = __ldg(&g4[(3 * BDIM + b) * (LDIM / 4) + i]);
            s4[i] = make_float4(p0.x + p1.x + p2.x + p3.x,
                                p0.y + p1.y + p2.y + p3.y,
                                p0.z + p1.z + p2.z + p3.z,
                                p0.w + p1.w + p2.w + p3.w);
        }
    }
    __syncthreads();

    const int l = tile * 512 + t * 2;
    const float evinv = g_evinv;
    float2 e2 = *reinterpret_cast<const float2*>(ev + l);
    const float ex = e2.x * evinv, ey = e2.y * evinv;

#pragma unroll
    for (int k = 0; k < KDIM; ++k) {
        int2 id = *reinterpret_cast<const int2*>(idxm + k * LDIM + l);
        float2 r = make_float2(s_xs[id.x] * ex, s_xs[id.y] * ey);
        *reinterpret_cast<float2*>(&g_adj[((size_t)b * KDIM + k) * LDIM + l]) = r;
    }
}

// ---------------------------------------------------------------------------
// Kernel C: out[b,o,l] = sum_k wcn[o,k] * adj[b,k,l] + bias[o]
// grid: (16 l-tiles of 256, 32 b, 2 o-chunks of 64) = 1024 blocks x 128 thr.
// Contiguous adj loads, scalar FFMA, padded scalar weight rows in smem.
// ---------------------------------------------------------------------------
__global__ __launch_bounds__(128) void gmconv_main_kernel(
    const float* __restrict__ bias,
    float*       __restrict__ out) {

    __shared__ float s_w[OCHUNK * WSTRIDE];    // 3 KB: w0..8, bias, pad, pad

    const int tile  = blockIdx.x;              // 0..15
    const int b     = blockIdx.y;              // 0..31
    const int obase = blockIdx.z * OCHUNK;     // 0, 64
    const int t     = threadIdx.x;

    // stage padded weight rows (tiny, L2-hot)
    for (int i = t; i < OCHUNK * WSTRIDE; i += 128) {
        int o = i / WSTRIDE, s = i - o * WSTRIDE;
        s_w[i] = (s < KDIM) ? g_wcn[(obase + o) * KDIM + s]
                            : (s == KDIM ? bias[obase + o] : 0.f);
    }
    __syncthreads();

    const int l = tile * 256 + t * 2;

    // 9 coalesced adj pair loads (L2-resident)
    float ax[KDIM], ay[KDIM];
#pragma unroll
    for (int k = 0; k < KDIM; ++k) {
        float2 v = *reinterpret_cast<const float2*>(
            &g_adj[((size_t)b * KDIM + k) * LDIM + l]);
        ax[k] = v.x; ay[k] = v.y;
    }

    float* outp = out + ((size_t)b * ODIM + obase) * LDIM + l;
#pragma unroll 4
    for (int o = 0; o < OCHUNK; ++o) {
        const float* wp = s_w + o * WSTRIDE;
        const float bo = wp[KDIM];
        float rx = bo, ry = bo;
#pragma unroll
        for (int k = 0; k < KDIM; ++k) {
            const float w = wp[k];             // smem broadcast, vectorizable
            rx = fmaf(w, ax[k], rx);
            ry = fmaf(w, ay[k], ry);
        }
        *reinterpret_cast<float2*>(outp + (size_t)o * LDIM) =
            make_float2(rx, ry);               // STG.64, coalesced
    }
}

// ---------------------------------------------------------------------------
extern "C" void kernel_launch(void* const* d_in, const int* in_sizes, int n_in,
                              void* d_out, int out_size) {
    const float* x    = nullptr;
    const float* wc   = nullptr;
    const float* ev   = nullptr;
    const float* bias = nullptr;
    const int*   idxm = nullptr;

    for (int i = 0; i < n_in; ++i) {
        switch (in_sizes[i]) {
            case BDIM * CIN * LDIM: x    = (const float*)d_in[i]; break;  // 8388608
            case ODIM * KDIM:       wc   = (const float*)d_in[i]; break;  // 1152
            case LDIM:              ev   = (const float*)d_in[i]; break;  // 4096
            case ODIM:              bias = (const float*)d_in[i]; break;  // 128
            case KDIM * LDIM:       idxm = (const int*)  d_in[i]; break;  // 36864
            default: break;
        }
    }

    float* out = (float*)d_out;

    reduce_prep_kernel<<<BDIM * 16 + 1, 256>>>(x, wc, ev);
    gather_kernel<<<dim3(8, BDIM), 256>>>(idxm, ev);
    gmconv_main_kernel<<<dim3(16, BDIM, 2), 128>>>(bias, out);
}

// round 7
// speedup vs baseline: 1.2143x; 1.2143x over previous
#include <cuda_runtime.h>
#include <cuda_bf16.h>

#define LDIM 4096
#define BDIM 32
#define CIN  64
#define ODIM 128
#define KDIM 9
#define CCHUNKS 2               // split-K chunks over channel dim
#define CPER   (CIN / CCHUNKS)  // 32 channels per chunk
#define OCHUNK 64               // outputs per main-kernel block
#define WSTRIDE 12              // padded weight row: w0..w8, bias, pad, pad

// Scratch (allocation-free rule: __device__ globals)
__device__ float g_part[CCHUNKS * BDIM * LDIM]; // partial channel sums, 1 MB
__device__ float g_wcn[ODIM * KDIM];            // normalized weight_coeff
__device__ float g_evinv;                       // 1 / ||err_vector||

// ---------------------------------------------------------------------------
// Kernel A: split-K channel reduction (512 blocks x 128 thr) + prep (block 512)
//   (identical to R4 config — warm wallclock ~4-5us)
// ---------------------------------------------------------------------------
__global__ __launch_bounds__(128) void reduce_prep_kernel(
    const float* __restrict__ x,
    const float* __restrict__ wc,
    const float* __restrict__ ev) {

    const int bx = blockIdx.x;
    const int t  = threadIdx.x;

    if (bx < BDIM * 16) {                      // 512 reduce blocks
        const int b   = bx >> 4;               // 0..31
        const int sub = bx & 15;
        const int lt  = sub >> 1;              // l-tile 0..7 (128 float4 each)
        const int cc  = sub & 1;               // channel chunk 0..1
        const int l4  = lt * 128 + t;          // 0..1023

        const float4* xp = reinterpret_cast<const float4*>(x) +
                           ((size_t)b * CIN + cc * CPER) * (LDIM / 4) + l4;
        float4 a0 = make_float4(0.f, 0.f, 0.f, 0.f);
        float4 a1 = make_float4(0.f, 0.f, 0.f, 0.f);
#pragma unroll 8
        for (int i = 0; i < CPER; i += 2) {
            float4 v0 = __ldg(xp + (i    ) * (LDIM / 4));
            float4 v1 = __ldg(xp + (i + 1) * (LDIM / 4));
            a0.x += v0.x; a0.y += v0.y; a0.z += v0.z; a0.w += v0.w;
            a1.x += v1.x; a1.y += v1.y; a1.z += v1.z; a1.w += v1.w;
        }
        a0.x += a1.x; a0.y += a1.y; a0.z += a1.z; a0.w += a1.w;
        reinterpret_cast<float4*>(g_part)[(cc * BDIM + b) * (LDIM / 4) + l4] = a0;
        return;
    }

    // ---- prep block (128 threads) ----
    __shared__ float red[128];
    float ssq = 0.f;
    for (int i = t; i < LDIM; i += 128) { float v = ev[i]; ssq += v * v; }
    red[t] = ssq;
    __syncthreads();
    for (int s = 64; s > 0; s >>= 1) {
        if (t < s) red[t] += red[t + s];
        __syncthreads();
    }
    if (t == 0) g_evinv = rsqrtf(red[0]);

    // one thread per output channel (128 threads = ODIM)
    {
        float w[KDIM];
        float n = 0.f;
#pragma unroll
        for (int k = 0; k < KDIM; ++k) { w[k] = wc[t * KDIM + k]; n += w[k] * w[k]; }
        float inv = rsqrtf(n);
#pragma unroll
        for (int k = 0; k < KDIM; ++k) g_wcn[t * KDIM + k] = w[k] * inv;
    }
}

// ---------------------------------------------------------------------------
// Kernel B: out[b,o,l] = ev[l]/||ev|| * sum_k wcn[o,k]*xs[b, idx[k,l]] + bias[o]
// grid: (8 l-tiles of 512, 32 b, 2 o-chunks of 64) = 512 blocks x 256 thr.
// Same block count / duplication as R4, but 2x warps per SM (occ 21.5 -> 43%).
// lpt=2: each thread owns one float2 pair of l.
// ---------------------------------------------------------------------------
__global__ __launch_bounds__(256) void gmconv_main_kernel(
    const int*   __restrict__ idxm,
    const float* __restrict__ ev,
    const float* __restrict__ bias,
    float*       __restrict__ out) {

    __shared__ float s_xs[LDIM];                    // 16 KB
    __shared__ float s_w[OCHUNK * WSTRIDE];         // 3 KB: w0..8, bias, pad

    const int tile  = blockIdx.x;                   // 0..7
    const int b     = blockIdx.y;                   // 0..31
    const int obase = blockIdx.z * OCHUNK;          // 0, 64
    const int t     = threadIdx.x;

    // stage xs[b] = p0 + p1 (L2-resident partials)
    {
        float4* s4 = reinterpret_cast<float4*>(s_xs);
        const float4* g4 = reinterpret_cast<const float4*>(g_part);
#pragma unroll
        for (int i = t; i < LDIM / 4; i += 256) {
            float4 p0 = __ldg(&g4[(0 * BDIM + b) * (LDIM / 4) + i]);
            float4 p1 = __ldg(&g4[(1 * BDIM + b) * (LDIM / 4) + i]);
            s4[i] = make_float4(p0.x + p1.x, p0.y + p1.y,
                                p0.z + p1.z, p0.w + p1.w);
        }
        // padded weight rows
#pragma unroll
        for (int i = t; i < OCHUNK * WSTRIDE; i += 256) {
            int o = i / WSTRIDE, s = i - o * WSTRIDE;
            s_w[i] = (s < KDIM) ? g_wcn[(obase + o) * KDIM + s]
                                : (s == KDIM ? bias[obase + o] : 0.f);
        }
    }
    __syncthreads();

    const int l = tile * 512 + t * 2;
    const float evinv = g_evinv;
    float2 e2 = __ldg(reinterpret_cast<const float2*>(ev + l));
    const float ex = e2.x * evinv, ey = e2.y * evinv;

    // gather 9 neighbor pairs per thread from smem, pre-scaled
    float gx[KDIM], gy[KDIM];
#pragma unroll
    for (int k = 0; k < KDIM; ++k) {
        int2 id = __ldg(reinterpret_cast<const int2*>(idxm + k * LDIM + l));
        gx[k] = s_xs[id.x] * ex;
        gy[k] = s_xs[id.y] * ey;
    }

    float* outp = out + ((size_t)b * ODIM + obase) * LDIM + l;
#pragma unroll 4
    for (int o = 0; o < OCHUNK; ++o) {
        const float* wp = s_w + o * WSTRIDE;
        const float bo = wp[KDIM];               // bias
        float rx = bo, ry = bo;
#pragma unroll
        for (int k = 0; k < KDIM; ++k) {
            const float w = wp[k];               // smem broadcast (vectorizable)
            rx = fmaf(w, gx[k], rx);
            ry = fmaf(w, gy[k], ry);
        }
        *reinterpret_cast<float2*>(outp + (size_t)o * LDIM) =
            make_float2(rx, ry);                 // STG.64, coalesced
    }
}

// ---------------------------------------------------------------------------
extern "C" void kernel_launch(void* const* d_in, const int* in_sizes, int n_in,
                              void* d_out, int out_size) {
    const float* x    = nullptr;
    const float* wc   = nullptr;
    const float* ev   = nullptr;
    const float* bias = nullptr;
    const int*   idxm = nullptr;

    for (int i = 0; i < n_in; ++i) {
        switch (in_sizes[i]) {
            case BDIM * CIN * LDIM: x    = (const float*)d_in[i]; break;  // 8388608
            case ODIM * KDIM:       wc   = (const float*)d_in[i]; break;  // 1152
            case LDIM:              ev   = (const float*)d_in[i]; break;  // 4096
            case ODIM:              bias = (const float*)d_in[i]; break;  // 128
            case KDIM * LDIM:       idxm = (const int*)  d_in[i]; break;  // 36864
            default: break;
        }
    }

    float* out = (float*)d_out;

    reduce_prep_kernel<<<BDIM * 16 + 1, 128>>>(x, wc, ev);
    gmconv_main_kernel<<<dim3(8, BDIM, 2), 256>>>(idxm, ev, bias, out);
}